// round 1
// baseline (speedup 1.0000x reference)
#include <cuda_runtime.h>
#include <math.h>

#define BB 4
#define CC 64
#define HH 64
#define WW 64
#define HW 4096
#define CHW (CC*HW)
#define EPSV 1e-5f
#define OFRV 4.0f
#define SCALEV 0.125f

// -------- scratch (device globals: no allocation allowed) --------
__device__ float g_q [BB*CHW];
__device__ float g_k [BB*CHW];
__device__ float g_v [BB*CHW];
__device__ float g_ao[BB*CHW];

// ================= conv1x1: y[b][o][p] = sum_c w[o][c]*x[b][c][p] + bias[o]
__device__ __forceinline__ void conv1x1_body(const float* __restrict__ x,
                                             const float* __restrict__ w,
                                             const float* __restrict__ bias,
                                             float* __restrict__ y) {
    __shared__ float ws[4096];
    __shared__ float bs[64];
    for (int i = threadIdx.x; i < 4096; i += 128) ws[i] = w[i];
    if (threadIdx.x < 64) bs[threadIdx.x] = bias[threadIdx.x];
    __syncthreads();
    int p  = blockIdx.x * 128 + threadIdx.x;
    int bb = blockIdx.y;
    const float* xb = x + bb * CHW + p;
    float xr[64];
#pragma unroll
    for (int c = 0; c < 64; c++) xr[c] = xb[c * HW];
    float* yb = y + bb * CHW + p;
    for (int o = 0; o < 64; o++) {
        float acc = bs[o];
#pragma unroll
        for (int c = 0; c < 64; c++) acc += ws[o * 64 + c] * xr[c];
        yb[o * HW] = acc;
    }
}

__global__ void k_convq(const float* __restrict__ prompt,
                        const float* __restrict__ wq,
                        const float* __restrict__ bq) {
    conv1x1_body(prompt, wq, bq, g_q);
}

__global__ void k_convo(const float* __restrict__ wo,
                        const float* __restrict__ bo,
                        float* __restrict__ out) {
    conv1x1_body(g_ao, wo, bo, out);
}

// ================= fused: depthwise3x3 + LN + GELU + offset + tanh
//                   + bilinear sample of kv + K/V projections
__global__ void k_fuse(const float* __restrict__ kv,
                       const float* __restrict__ dw_w,
                       const float* __restrict__ dw_b,
                       const float* __restrict__ ln_w,
                       const float* __restrict__ ln_b,
                       const float* __restrict__ off_w,
                       const float* __restrict__ wk,
                       const float* __restrict__ bk,
                       const float* __restrict__ wv,
                       const float* __restrict__ bv) {
    __shared__ float s_wk[4096], s_wv[4096];
    __shared__ float s_dw[576], s_dwb[64], s_lnw[64], s_lnb[64];
    __shared__ float s_offw[128], s_bk[64], s_bv[64];

    for (int i = threadIdx.x; i < 4096; i += 128) { s_wk[i] = wk[i]; s_wv[i] = wv[i]; }
    for (int i = threadIdx.x; i < 576; i += 128) s_dw[i] = dw_w[i];
    if (threadIdx.x < 64) {
        s_dwb[threadIdx.x] = dw_b[threadIdx.x];
        s_lnw[threadIdx.x] = ln_w[threadIdx.x];
        s_lnb[threadIdx.x] = ln_b[threadIdx.x];
        s_bk[threadIdx.x]  = bk[threadIdx.x];
        s_bv[threadIdx.x]  = bv[threadIdx.x];
    }
    if (threadIdx.x < 128) s_offw[threadIdx.x] = off_w[threadIdx.x];
    __syncthreads();

    int p  = blockIdx.x * 128 + threadIdx.x;
    int bb = blockIdx.y;
    int py = p >> 6;
    int px = p & 63;

    const float* qb = g_q + bb * CHW;

    float t[64];
#pragma unroll
    for (int c = 0; c < 64; c++) t[c] = s_dwb[c];

    // depthwise 3x3, zero padded
    for (int k9 = 0; k9 < 9; k9++) {
        int dy = k9 / 3 - 1, dx = k9 % 3 - 1;
        int yy = py + dy, xx = px + dx;
        if (yy < 0 || yy > 63 || xx < 0 || xx > 63) continue;
        const float* qp = qb + yy * 64 + xx;
#pragma unroll
        for (int c = 0; c < 64; c++) t[c] += qp[c * HW] * s_dw[c * 9 + k9];
    }

    // LayerNorm over channels
    float mu = 0.f;
#pragma unroll
    for (int c = 0; c < 64; c++) mu += t[c];
    mu *= (1.0f / 64.0f);
    float var = 0.f;
#pragma unroll
    for (int c = 0; c < 64; c++) { float d = t[c] - mu; var += d * d; }
    var *= (1.0f / 64.0f);
    float rstd = rsqrtf(var + EPSV);
#pragma unroll
    for (int c = 0; c < 64; c++) {
        float z = (t[c] - mu) * rstd * s_lnw[c] + s_lnb[c];
        // exact GELU
        t[c] = 0.5f * z * (1.0f + erff(z * 0.70710678118654752f));
    }

    // offset head (2 channels)
    float o0 = 0.f, o1 = 0.f;
#pragma unroll
    for (int c = 0; c < 64; c++) { o0 += s_offw[c] * t[c]; o1 += s_offw[64 + c] * t[c]; }
    float off0 = tanhf(o0) * (1.0f / 63.0f) * OFRV;   // y-direction
    float off1 = tanhf(o1) * (1.0f / 63.0f) * OFRV;   // x-direction

    float refy = (0.5f + (float)py) * (2.0f / 63.0f) - 1.0f;
    float refx = (0.5f + (float)px) * (2.0f / 63.0f) - 1.0f;
    float gx = (off1 + refx + 1.0f) * 0.5f * 63.0f;
    float gy = (off0 + refy + 1.0f) * 0.5f * 63.0f;

    float x0f = floorf(gx), y0f = floorf(gy);
    float wx = gx - x0f, wy = gy - y0f;
    int x0 = (int)x0f, y0 = (int)y0f;
    int x1 = x0 + 1,   y1 = y0 + 1;

    float m00 = (x0 >= 0 && x0 <= 63 && y0 >= 0 && y0 <= 63) ? 1.f : 0.f;
    float m01 = (x1 >= 0 && x1 <= 63 && y0 >= 0 && y0 <= 63) ? 1.f : 0.f;
    float m10 = (x0 >= 0 && x0 <= 63 && y1 >= 0 && y1 <= 63) ? 1.f : 0.f;
    float m11 = (x1 >= 0 && x1 <= 63 && y1 >= 0 && y1 <= 63) ? 1.f : 0.f;

    int xc0 = min(max(x0, 0), 63), xc1 = min(max(x1, 0), 63);
    int yc0 = min(max(y0, 0), 63), yc1 = min(max(y1, 0), 63);

    float w00 = m00 * (1.0f - wx) * (1.0f - wy);
    float w01 = m01 * wx * (1.0f - wy);
    float w10 = m10 * (1.0f - wx) * wy;
    float w11 = m11 * wx * wy;

    int i00 = yc0 * 64 + xc0, i01 = yc0 * 64 + xc1;
    int i10 = yc1 * 64 + xc0, i11 = yc1 * 64 + xc1;

    const float* kvb = kv + bb * CHW;
#pragma unroll
    for (int c = 0; c < 64; c++) {
        const float* kc = kvb + c * HW;
        t[c] = w00 * kc[i00] + w01 * kc[i01] + w10 * kc[i10] + w11 * kc[i11];
    }

    // K/V projections
    float* kout = g_k + bb * CHW + p;
    float* vout = g_v + bb * CHW + p;
    for (int o = 0; o < 64; o++) {
        float ka = s_bk[o], va = s_bv[o];
#pragma unroll
        for (int c = 0; c < 64; c++) {
            ka += s_wk[o * 64 + c] * t[c];
            va += s_wv[o * 64 + c] * t[c];
        }
        kout[o * HW] = ka;
        vout[o * HW] = va;
    }
}

// ================= flash-attention (fp32), 64-query tile per CTA
// smem layout (floats): Qs[64*64] | KP[64*65] (K tile, reused as P) | Vs[64*65] | m,l,a[64 each]
#define ATTN_SMEM ((4096 + 4160 + 4160 + 192) * 4)

__global__ void k_attn() {
    extern __shared__ float sm[];
    float* Qs  = sm;                 // [c][q], stride 64
    float* KP  = sm + 4096;          // [c][n] stride 65; later P [q][n] stride 65
    float* Vs  = sm + 4096 + 4160;   // [n][c], stride 65
    float* s_m = Vs + 4160;
    float* s_l = s_m + 64;
    float* s_a = s_l + 64;

    int tid = threadIdx.x;
    int bb  = blockIdx.y;
    int m0  = blockIdx.x * 64;

    const float* qb = g_q + bb * CHW;
    const float* kb = g_k + bb * CHW;
    const float* vb = g_v + bb * CHW;

    for (int i = tid; i < 4096; i += 256) {
        int c = i >> 6, qq = i & 63;
        Qs[c * 64 + qq] = qb[c * HW + m0 + qq];
    }
    if (tid < 64) { s_m[tid] = -1e30f; s_l[tid] = 0.f; }

    int qb4 = (tid >> 4) << 2;   // query base (0..60)
    int nb4 = (tid & 15) << 2;   // key/channel base (0..60)

    float oacc[4][4];
#pragma unroll
    for (int i = 0; i < 4; i++)
#pragma unroll
        for (int j = 0; j < 4; j++) oacc[i][j] = 0.f;

    __syncthreads();

    for (int kt = 0; kt < 64; kt++) {
        int n0 = kt * 64;
        for (int i = tid; i < 4096; i += 256) {
            int c = i >> 6, nn = i & 63;
            float kvv = kb[c * HW + n0 + nn];
            float vvv = vb[c * HW + n0 + nn];
            KP[c * 65 + nn] = kvv;
            Vs[nn * 65 + c] = vvv;     // transposed V tile
        }
        __syncthreads();

        // S = Q^T K (4x4 per thread)
        float sacc[4][4];
#pragma unroll
        for (int i = 0; i < 4; i++)
#pragma unroll
            for (int j = 0; j < 4; j++) sacc[i][j] = 0.f;
#pragma unroll
        for (int c = 0; c < 64; c++) {
            float qv[4], kk[4];
#pragma unroll
            for (int i = 0; i < 4; i++) qv[i] = Qs[c * 64 + qb4 + i];
#pragma unroll
            for (int j = 0; j < 4; j++) kk[j] = KP[c * 65 + nb4 + j];
#pragma unroll
            for (int i = 0; i < 4; i++)
#pragma unroll
                for (int j = 0; j < 4; j++) sacc[i][j] += qv[i] * kk[j];
        }
        __syncthreads();   // everyone done reading K before overwriting with P

#pragma unroll
        for (int i = 0; i < 4; i++)
#pragma unroll
            for (int j = 0; j < 4; j++)
                KP[(qb4 + i) * 65 + nb4 + j] = sacc[i][j] * SCALEV;
        __syncthreads();

        // online softmax (one thread per query row)
        if (tid < 64) {
            float* row = KP + tid * 65;
            float mold = s_m[tid];
            float mx = mold;
#pragma unroll
            for (int n = 0; n < 64; n++) mx = fmaxf(mx, row[n]);
            float alpha = expf(mold - mx);
            float ls = 0.f;
#pragma unroll
            for (int n = 0; n < 64; n++) {
                float e = expf(row[n] - mx);
                row[n] = e;
                ls += e;
            }
            s_l[tid] = s_l[tid] * alpha + ls;
            s_m[tid] = mx;
            s_a[tid] = alpha;
        }
        __syncthreads();

        // rescale O and accumulate P @ V^T
#pragma unroll
        for (int i = 0; i < 4; i++) {
            float a = s_a[qb4 + i];
#pragma unroll
            for (int j = 0; j < 4; j++) oacc[i][j] *= a;
        }
#pragma unroll
        for (int n = 0; n < 64; n++) {
            float pv[4], vv[4];
#pragma unroll
            for (int i = 0; i < 4; i++) pv[i] = KP[(qb4 + i) * 65 + n];
#pragma unroll
            for (int j = 0; j < 4; j++) vv[j] = Vs[n * 65 + nb4 + j];
#pragma unroll
            for (int i = 0; i < 4; i++)
#pragma unroll
                for (int j = 0; j < 4; j++) oacc[i][j] += pv[i] * vv[j];
        }
        __syncthreads();
    }

    // write out[b][c][m] = O / l
    float* ob = g_ao + bb * CHW;
#pragma unroll
    for (int i = 0; i < 4; i++) {
        float inv = 1.0f / s_l[qb4 + i];
#pragma unroll
        for (int j = 0; j < 4; j++)
            ob[(nb4 + j) * HW + m0 + qb4 + i] = oacc[i][j] * inv;
    }
}

// ================= launch =================
extern "C" void kernel_launch(void* const* d_in, const int* in_sizes, int n_in,
                              void* d_out, int out_size) {
    const float* prompt = (const float*)d_in[0];
    const float* kv     = (const float*)d_in[1];
    const float* wq     = (const float*)d_in[2];
    const float* bq     = (const float*)d_in[3];
    const float* wk     = (const float*)d_in[4];
    const float* bk     = (const float*)d_in[5];
    const float* wv     = (const float*)d_in[6];
    const float* bv     = (const float*)d_in[7];
    const float* wo     = (const float*)d_in[8];
    const float* bo     = (const float*)d_in[9];
    const float* dw_w   = (const float*)d_in[10];
    const float* dw_b   = (const float*)d_in[11];
    const float* ln_w   = (const float*)d_in[12];
    const float* ln_b   = (const float*)d_in[13];
    const float* off_w  = (const float*)d_in[14];
    float* out = (float*)d_out;

    cudaFuncSetAttribute(k_attn, cudaFuncAttributeMaxDynamicSharedMemorySize, ATTN_SMEM);

    dim3 g32(32, BB);
    k_convq<<<g32, 128>>>(prompt, wq, bq);
    k_fuse <<<g32, 128>>>(kv, dw_w, dw_b, ln_w, ln_b, off_w, wk, bk, wv, bv);
    k_attn <<<dim3(64, BB), 256, ATTN_SMEM>>>();
    k_convo<<<g32, 128>>>(wo, bo, out);
}

// round 3
// speedup vs baseline: 3.0335x; 3.0335x over previous
#include <cuda_runtime.h>
#include <math.h>
#include <stdint.h>

#define BB 4
#define CC 64
#define HW 4096
#define CHW (CC*HW)
#define EPSV 1e-5f
#define OFRV 4.0f
#define SCALEV 0.125f

// -------- scratch (device globals) --------
__device__ float g_q [BB*CHW];   // [b][p][c]  query,  pixel-major
__device__ float g_k [BB*CHW];   // [b][n][c]  key,    pixel-major
__device__ float g_v [BB*CHW];   // [b][n][c]  value,  pixel-major
__device__ float g_ao[BB*CHW];   // [b][p][c]  attn out, pixel-major

// ================= helpers =================
__device__ __forceinline__ uint32_t smem_u32(const void* p){
    uint32_t a;
    asm("{ .reg .u64 t; cvta.to.shared.u64 t, %1; cvt.u32.u64 %0, t; }" : "=r"(a) : "l"(p));
    return a;
}
__device__ __forceinline__ void cp16(uint32_t dst, const void* src){
    asm volatile("cp.async.cg.shared.global [%0], [%1], 16;" :: "r"(dst), "l"(src));
}
#define CP_COMMIT() asm volatile("cp.async.commit_group;" ::: "memory")
#define CP_WAIT0()  asm volatile("cp.async.wait_group 0;" ::: "memory")
#define CP_WAIT1()  asm volatile("cp.async.wait_group 1;" ::: "memory")

__device__ __forceinline__ void mma_tf32(float* d, const uint32_t* a,
                                         uint32_t b0, uint32_t b1, const float* c){
    asm volatile(
        "mma.sync.aligned.m16n8k8.row.col.f32.tf32.tf32.f32 "
        "{%0,%1,%2,%3}, {%4,%5,%6,%7}, {%8,%9}, {%10,%11,%12,%13};"
        : "=f"(d[0]), "=f"(d[1]), "=f"(d[2]), "=f"(d[3])
        : "r"(a[0]), "r"(a[1]), "r"(a[2]), "r"(a[3]),
          "r"(b0), "r"(b1),
          "f"(c[0]), "f"(c[1]), "f"(c[2]), "f"(c[3]));
}

// ================= conv1x1 q: prompt [c][p] -> g_q [p][c]
__global__ void k_convq(const float* __restrict__ prompt,
                        const float* __restrict__ wq,
                        const float* __restrict__ bq) {
    __shared__ float ws[4096];
    __shared__ float bs[64];
    int tid = threadIdx.x;
    for (int i = tid; i < 4096; i += 256) ws[i] = wq[i];
    if (tid < 64) bs[tid] = bq[tid];
    __syncthreads();
    int half = tid >> 7;
    int p  = blockIdx.x * 128 + (tid & 127);
    int bb = blockIdx.y;
    const float* xb = prompt + bb * CHW + p;
    float xr[64];
#pragma unroll
    for (int c = 0; c < 64; c++) xr[c] = xb[c * HW];
    float4* yb = (float4*)(g_q + bb * CHW + p * 64 + half * 32);
    const float* wbase = ws + half * 32 * 64;
    for (int o4 = 0; o4 < 8; o4++) {
        float a0 = bs[half*32 + o4*4 + 0], a1 = bs[half*32 + o4*4 + 1];
        float a2 = bs[half*32 + o4*4 + 2], a3 = bs[half*32 + o4*4 + 3];
#pragma unroll
        for (int c = 0; c < 64; c++) {
            float x = xr[c];
            a0 += wbase[(o4*4+0)*64 + c] * x;
            a1 += wbase[(o4*4+1)*64 + c] * x;
            a2 += wbase[(o4*4+2)*64 + c] * x;
            a3 += wbase[(o4*4+3)*64 + c] * x;
        }
        yb[o4] = make_float4(a0, a1, a2, a3);
    }
}

// ================= conv1x1 out: g_ao [p][c] -> out [c][p]
__global__ void k_convo(const float* __restrict__ wo,
                        const float* __restrict__ bo,
                        float* __restrict__ out) {
    __shared__ float ws[4096];
    __shared__ float bs[64];
    int tid = threadIdx.x;
    for (int i = tid; i < 4096; i += 256) ws[i] = wo[i];
    if (tid < 64) bs[tid] = bo[tid];
    __syncthreads();
    int half = tid >> 7;
    int p  = blockIdx.x * 128 + (tid & 127);
    int bb = blockIdx.y;
    const float4* xb4 = (const float4*)(g_ao + bb * CHW + p * 64);
    float xr[64];
#pragma unroll
    for (int c4 = 0; c4 < 16; c4++) {
        float4 v = xb4[c4];
        xr[c4*4+0] = v.x; xr[c4*4+1] = v.y; xr[c4*4+2] = v.z; xr[c4*4+3] = v.w;
    }
    float* yb = out + bb * CHW + (half * 32) * HW + p;
    const float* wbase = ws + half * 32 * 64;
    for (int o = 0; o < 32; o++) {
        float acc = bs[half*32 + o];
#pragma unroll
        for (int c = 0; c < 64; c++) acc += wbase[o*64 + c] * xr[c];
        yb[o * HW] = acc;
    }
}

// ================= fused: dw3x3 + LN + GELU + offset + tanh + bilinear + K/V proj
__global__ void k_fuse(const float* __restrict__ kv,
                       const float* __restrict__ dw_w,
                       const float* __restrict__ dw_b,
                       const float* __restrict__ ln_w,
                       const float* __restrict__ ln_b,
                       const float* __restrict__ off_w,
                       const float* __restrict__ wk,
                       const float* __restrict__ bk,
                       const float* __restrict__ wv,
                       const float* __restrict__ bv) {
    __shared__ float s_wk[4096], s_wv[4096];
    __shared__ float s_dw[576], s_dwb[64], s_lnw[64], s_lnb[64];
    __shared__ float s_offw[128], s_bk[64], s_bv[64];

    for (int i = threadIdx.x; i < 4096; i += 128) { s_wk[i] = wk[i]; s_wv[i] = wv[i]; }
    for (int i = threadIdx.x; i < 576; i += 128) s_dw[i] = dw_w[i];
    if (threadIdx.x < 64) {
        s_dwb[threadIdx.x] = dw_b[threadIdx.x];
        s_lnw[threadIdx.x] = ln_w[threadIdx.x];
        s_lnb[threadIdx.x] = ln_b[threadIdx.x];
        s_bk[threadIdx.x]  = bk[threadIdx.x];
        s_bv[threadIdx.x]  = bv[threadIdx.x];
    }
    if (threadIdx.x < 128) s_offw[threadIdx.x] = off_w[threadIdx.x];
    __syncthreads();

    int p  = blockIdx.x * 128 + threadIdx.x;
    int bb = blockIdx.y;
    int py = p >> 6;
    int px = p & 63;

    const float* qb = g_q + bb * CHW;   // [p][c]

    float t[64];
#pragma unroll
    for (int c = 0; c < 64; c++) t[c] = s_dwb[c];

    for (int k9 = 0; k9 < 9; k9++) {
        int dy = k9 / 3 - 1, dx = k9 % 3 - 1;
        int yy = py + dy, xx = px + dx;
        if (yy < 0 || yy > 63 || xx < 0 || xx > 63) continue;
        const float4* qp = (const float4*)(qb + (yy * 64 + xx) * 64);
#pragma unroll
        for (int c4 = 0; c4 < 16; c4++) {
            float4 qv = qp[c4];
            t[c4*4+0] += qv.x * s_dw[(c4*4+0)*9 + k9];
            t[c4*4+1] += qv.y * s_dw[(c4*4+1)*9 + k9];
            t[c4*4+2] += qv.z * s_dw[(c4*4+2)*9 + k9];
            t[c4*4+3] += qv.w * s_dw[(c4*4+3)*9 + k9];
        }
    }

    float mu = 0.f;
#pragma unroll
    for (int c = 0; c < 64; c++) mu += t[c];
    mu *= (1.0f / 64.0f);
    float var = 0.f;
#pragma unroll
    for (int c = 0; c < 64; c++) { float d = t[c] - mu; var += d * d; }
    var *= (1.0f / 64.0f);
    float rstd = rsqrtf(var + EPSV);
#pragma unroll
    for (int c = 0; c < 64; c++) {
        float z = (t[c] - mu) * rstd * s_lnw[c] + s_lnb[c];
        t[c] = 0.5f * z * (1.0f + erff(z * 0.70710678118654752f));
    }

    float o0 = 0.f, o1 = 0.f;
#pragma unroll
    for (int c = 0; c < 64; c++) { o0 += s_offw[c] * t[c]; o1 += s_offw[64 + c] * t[c]; }
    float off0 = tanhf(o0) * (1.0f / 63.0f) * OFRV;
    float off1 = tanhf(o1) * (1.0f / 63.0f) * OFRV;

    float refy = (0.5f + (float)py) * (2.0f / 63.0f) - 1.0f;
    float refx = (0.5f + (float)px) * (2.0f / 63.0f) - 1.0f;
    float gx = (off1 + refx + 1.0f) * 0.5f * 63.0f;
    float gy = (off0 + refy + 1.0f) * 0.5f * 63.0f;

    float x0f = floorf(gx), y0f = floorf(gy);
    float wx = gx - x0f, wy = gy - y0f;
    int x0 = (int)x0f, y0 = (int)y0f;
    int x1 = x0 + 1,   y1 = y0 + 1;

    float m00 = (x0 >= 0 && x0 <= 63 && y0 >= 0 && y0 <= 63) ? 1.f : 0.f;
    float m01 = (x1 >= 0 && x1 <= 63 && y0 >= 0 && y0 <= 63) ? 1.f : 0.f;
    float m10 = (x0 >= 0 && x0 <= 63 && y1 >= 0 && y1 <= 63) ? 1.f : 0.f;
    float m11 = (x1 >= 0 && x1 <= 63 && y1 >= 0 && y1 <= 63) ? 1.f : 0.f;

    int xc0 = min(max(x0, 0), 63), xc1 = min(max(x1, 0), 63);
    int yc0 = min(max(y0, 0), 63), yc1 = min(max(y1, 0), 63);

    float w00 = m00 * (1.0f - wx) * (1.0f - wy);
    float w01 = m01 * wx * (1.0f - wy);
    float w10 = m10 * (1.0f - wx) * wy;
    float w11 = m11 * wx * wy;

    int i00 = yc0 * 64 + xc0, i01 = yc0 * 64 + xc1;
    int i10 = yc1 * 64 + xc0, i11 = yc1 * 64 + xc1;

    const float* kvb = kv + bb * CHW;
#pragma unroll
    for (int c = 0; c < 64; c++) {
        const float* kc = kvb + c * HW;
        t[c] = w00 * kc[i00] + w01 * kc[i01] + w10 * kc[i10] + w11 * kc[i11];
    }

    float* kout = g_k + bb * CHW + p * 64;   // [n][c]
    float* vout = g_v + bb * CHW + p * 64;   // [n][c]
    for (int o4 = 0; o4 < 16; o4++) {
        float ka[4], va[4];
#pragma unroll
        for (int i = 0; i < 4; i++) { ka[i] = s_bk[o4*4+i]; va[i] = s_bv[o4*4+i]; }
#pragma unroll
        for (int c = 0; c < 64; c++) {
            float x = t[c];
#pragma unroll
            for (int i = 0; i < 4; i++) {
                ka[i] += s_wk[(o4*4+i)*64 + c] * x;
                va[i] += s_wv[(o4*4+i)*64 + c] * x;
            }
        }
        ((float4*)kout)[o4] = make_float4(ka[0], ka[1], ka[2], ka[3]);
        ((float4*)vout)[o4] = make_float4(va[0], va[1], va[2], va[3]);
    }
}

// ================= mma.sync tf32 flash attention =================
// 256 thr = 8 warps. M=128 queries/CTA (16 per warp). 64-key tiles, double-buffered.
// smem floats: K 64x68 (x2), V 64x72 (x2), P 128x68
#define KSTR 68
#define VSTR 72
#define PSTR 68
#define KS0 0
#define KS1 (64*KSTR)
#define VS0 (2*64*KSTR)
#define VS1 (2*64*KSTR + 64*VSTR)
#define PS  (2*64*KSTR + 2*64*VSTR)
#define ATTN_SMEM ((2*64*KSTR + 2*64*VSTR + 128*PSTR) * 4)

__global__ void __launch_bounds__(256) k_attn() {
    extern __shared__ float sm[];
    int tid  = threadIdx.x;
    int wid  = tid >> 5;
    int lane = tid & 31;
    int qr   = lane >> 2;   // 0..7
    int qc   = lane & 3;    // 0..3
    int bb = blockIdx.y;
    int m0 = blockIdx.x * 128;

    const float* qb = g_q + bb * CHW;
    const float* kb = g_k + bb * CHW;
    const float* vb = g_v + bb * CHW;

    uint32_t sbase = smem_u32(sm);

    // ---- Q fragments (persist in registers) ----
    uint32_t aq[8][4];
    {
        const float* qw = qb + (m0 + wid * 16) * 64;
#pragma unroll
        for (int kc = 0; kc < 8; kc++) {
            aq[kc][0] = __float_as_uint(qw[ qr      * 64 + kc*8 + qc    ]);
            aq[kc][1] = __float_as_uint(qw[(qr + 8) * 64 + kc*8 + qc    ]);
            aq[kc][2] = __float_as_uint(qw[ qr      * 64 + kc*8 + qc + 4]);
            aq[kc][3] = __float_as_uint(qw[(qr + 8) * 64 + kc*8 + qc + 4]);
        }
    }

    float oacc[8][4];
#pragma unroll
    for (int nc = 0; nc < 8; nc++)
#pragma unroll
        for (int j = 0; j < 4; j++) oacc[nc][j] = 0.f;
    float rs0 = 0.f, rs1 = 0.f;

    // ---- prefetch tile 0 ----
    {
        const float* ks = kb;
        const float* vs = vb;
#pragma unroll
        for (int it = 0; it < 4; it++) {
            int idx = tid + it * 256;          // 0..1023
            int key = idx >> 4, c4 = idx & 15;
            cp16(sbase + (KS0 + key * KSTR + c4 * 4) * 4, ks + key * 64 + c4 * 4);
            cp16(sbase + (VS0 + key * VSTR + c4 * 4) * 4, vs + key * 64 + c4 * 4);
        }
        CP_COMMIT();
    }

    float* Pw = sm + PS + (wid * 16) * PSTR;   // this warp's 16 P rows

    for (int i = 0; i < 64; i++) {
        __syncthreads();   // previous iteration fully done before overwriting its buffers
        if (i + 1 < 64) {
            const float* ks = kb + (i + 1) * 4096;
            const float* vs = vb + (i + 1) * 4096;
            uint32_t ko = ((i + 1) & 1) ? KS1 : KS0;
            uint32_t vo = ((i + 1) & 1) ? VS1 : VS0;
#pragma unroll
            for (int it = 0; it < 4; it++) {
                int idx = tid + it * 256;
                int key = idx >> 4, c4 = idx & 15;
                cp16(sbase + (ko + key * KSTR + c4 * 4) * 4, ks + key * 64 + c4 * 4);
                cp16(sbase + (vo + key * VSTR + c4 * 4) * 4, vs + key * 64 + c4 * 4);
            }
            CP_COMMIT();
            CP_WAIT1();
        } else {
            CP_WAIT0();
        }
        __syncthreads();   // current tile ready for all warps

        const float* Ks = sm + ((i & 1) ? KS1 : KS0);
        const float* Vs = sm + ((i & 1) ? VS1 : VS0);

        // ---- S = Q @ K^T, exp, P -> smem, rowsum ----
#pragma unroll
        for (int nc = 0; nc < 8; nc++) {
            float s[4] = {0.f, 0.f, 0.f, 0.f};
            const float* kr0 = Ks + (nc * 8 + qr) * KSTR + qc;
#pragma unroll
            for (int kc = 0; kc < 8; kc++) {
                uint32_t b0 = __float_as_uint(kr0[kc * 8]);
                uint32_t b1 = __float_as_uint(kr0[kc * 8 + 4]);
                mma_tf32(s, aq[kc], b0, b1, s);
            }
            float e0 = __expf(s[0] * SCALEV);
            float e1 = __expf(s[1] * SCALEV);
            float e2 = __expf(s[2] * SCALEV);
            float e3 = __expf(s[3] * SCALEV);
            rs0 += e0 + e1;
            rs1 += e2 + e3;
            *(float2*)(Pw +  qr      * PSTR + nc * 8 + 2 * qc) = make_float2(e0, e1);
            *(float2*)(Pw + (qr + 8) * PSTR + nc * 8 + 2 * qc) = make_float2(e2, e3);
        }
        __syncwarp();   // P rows are warp-private: warp-level sync suffices

        // ---- P fragments ----
        uint32_t ap[8][4];
#pragma unroll
        for (int kc = 0; kc < 8; kc++) {
            ap[kc][0] = __float_as_uint(Pw[ qr      * PSTR + kc*8 + qc    ]);
            ap[kc][1] = __float_as_uint(Pw[(qr + 8) * PSTR + kc*8 + qc    ]);
            ap[kc][2] = __float_as_uint(Pw[ qr      * PSTR + kc*8 + qc + 4]);
            ap[kc][3] = __float_as_uint(Pw[(qr + 8) * PSTR + kc*8 + qc + 4]);
        }

        // ---- O += P @ V ----
#pragma unroll
        for (int nc = 0; nc < 8; nc++) {
            const float* vr0 = Vs + qc * VSTR + nc * 8 + qr;
#pragma unroll
            for (int kc = 0; kc < 8; kc++) {
                uint32_t b0 = __float_as_uint(vr0[(kc * 8    ) * VSTR]);
                uint32_t b1 = __float_as_uint(vr0[(kc * 8 + 4) * VSTR]);
                mma_tf32(oacc[nc], ap[kc], b0, b1, oacc[nc]);
            }
        }
    }

    // ---- softmax normalization (rows are warp-exclusive) ----
    rs0 += __shfl_xor_sync(0xffffffffu, rs0, 1);
    rs0 += __shfl_xor_sync(0xffffffffu, rs0, 2);
    rs1 += __shfl_xor_sync(0xffffffffu, rs1, 1);
    rs1 += __shfl_xor_sync(0xffffffffu, rs1, 2);
    float inv0 = 1.0f / rs0;
    float inv1 = 1.0f / rs1;

    float* ob = g_ao + bb * CHW + (m0 + wid * 16) * 64;
#pragma unroll
    for (int nc = 0; nc < 8; nc++) {
        *(float2*)(ob +  qr      * 64 + nc * 8 + 2 * qc) =
            make_float2(oacc[nc][0] * inv0, oacc[nc][1] * inv0);
        *(float2*)(ob + (qr + 8) * 64 + nc * 8 + 2 * qc) =
            make_float2(oacc[nc][2] * inv1, oacc[nc][3] * inv1);
    }
}

// ================= launch =================
extern "C" void kernel_launch(void* const* d_in, const int* in_sizes, int n_in,
                              void* d_out, int out_size) {
    const float* prompt = (const float*)d_in[0];
    const float* kv     = (const float*)d_in[1];
    const float* wq     = (const float*)d_in[2];
    const float* bq     = (const float*)d_in[3];
    const float* wk     = (const float*)d_in[4];
    const float* bk     = (const float*)d_in[5];
    const float* wv     = (const float*)d_in[6];
    const float* bv     = (const float*)d_in[7];
    const float* wo     = (const float*)d_in[8];
    const float* bo     = (const float*)d_in[9];
    const float* dw_w   = (const float*)d_in[10];
    const float* dw_b   = (const float*)d_in[11];
    const float* ln_w   = (const float*)d_in[12];
    const float* ln_b   = (const float*)d_in[13];
    const float* off_w  = (const float*)d_in[14];
    float* out = (float*)d_out;

    cudaFuncSetAttribute(k_attn, cudaFuncAttributeMaxDynamicSharedMemorySize, ATTN_SMEM);

    k_convq<<<dim3(32, BB), 256>>>(prompt, wq, bq);
    k_fuse <<<dim3(32, BB), 128>>>(kv, dw_w, dw_b, ln_w, ln_b, off_w, wk, bk, wv, bv);
    k_attn <<<dim3(32, BB), 256, ATTN_SMEM>>>();
    k_convo<<<dim3(32, BB), 256>>>(wo, bo, out);
}